// round 13
// baseline (speedup 1.0000x reference)
#include <cuda_runtime.h>
#include <cuda_bf16.h>
#include <cstdint>

// ============================================================================
// BlockSparseLinear: out[M=8192, N=4096] = x[M, K=4096] @ (W .* mask)^T + bias
// mask: 16x16 uniform blocks, ~10% nonzero.
//
// R13 == R8 resubmit (R8-R12 hit GPU-broker acquisition timeouts; pre-build,
// infra-side — the kernel has never been compiled or run):
//   CTA = 16 warps = 16 CONSECUTIVE obs x SAME 64-row m-slice (512 thr).
//   All warps read the same (kb, mtile) x fragments when k-lists overlap
//   (union(16) ~ 81.5% vs 160% naive) -> x L2 traffic ~halved.
//   - detect_mask parallel, build_slots, prep_w, prep_x: validated R6/R7
//   - 3-term product xh*wh + xh*wl + xl*wh  (rel err 4.7e-6, validated)
// ============================================================================

#define KDIM 4096
#define NDIM 4096
#define NOB  256

__device__ int g_gt1, g_pair;          // sticky detection flags (idempotent)
__device__ int g_obcnt[NOB];
__device__ unsigned char g_oblist[NOB * 256];
// w fragments: per ob, per slot: [hi: 32 x uint4][lo: 32 x uint4] = 1 KB
__device__ __align__(16) uint4 g_wc4[(size_t)NOB * 256 * 64];
// x fragments: per (kb, mtile16): [hi: 32 x uint4][lo: 32 x uint4] = 1 KB
__device__ __align__(16) uint4 g_xf[(size_t)256 * 512 * 64];

// ---------------------------------------------------------------------------
__device__ __forceinline__ void split2(float a, float b, uint32_t& h, uint32_t& l) {
    __nv_bfloat162 hh = __floats2bfloat162_rn(a, b);
    uint32_t hu = *reinterpret_cast<uint32_t*>(&hh);
    float af = __uint_as_float(hu << 16);
    float bf = __uint_as_float(hu & 0xFFFF0000u);
    __nv_bfloat162 ll = __floats2bfloat162_rn(a - af, b - bf);
    h = hu;
    l = *reinterpret_cast<uint32_t*>(&ll);
}

__device__ __forceinline__ void mma16816(float* c, const uint32_t* a,
                                         uint32_t b0, uint32_t b1) {
    asm volatile("mma.sync.aligned.m16n8k16.row.col.f32.bf16.bf16.f32 "
                 "{%0,%1,%2,%3}, {%4,%5,%6,%7}, {%8,%9}, {%0,%1,%2,%3};"
                 : "+f"(c[0]), "+f"(c[1]), "+f"(c[2]), "+f"(c[3])
                 : "r"(a[0]), "r"(a[1]), "r"(a[2]), "r"(a[3]), "r"(b0), "r"(b1));
}

// ---------------------------------------------------------------------------
// Mask dtype detection — parallel (validated R6).
// ---------------------------------------------------------------------------
__global__ void detect_mask_kernel(const unsigned char* __restrict__ mask) {
    size_t base = ((size_t)blockIdx.x * blockDim.x + threadIdx.x) * 8;
    uint64_t v = *(const uint64_t*)(mask + base);
    unsigned char nxt = mask[base + 8];
    bool gt1 = false, pair = false;
#pragma unroll
    for (int j = 0; j < 8; ++j) {
        unsigned char a = (unsigned char)(v >> (8 * j));
        unsigned char b = (j < 7) ? (unsigned char)(v >> (8 * (j + 1))) : nxt;
        gt1 |= (a > 1);
        pair |= (a == 1 && b == 1);
    }
    unsigned bg = __ballot_sync(0xFFFFFFFFu, gt1);
    unsigned bp = __ballot_sync(0xFFFFFFFFu, pair);
    if ((threadIdx.x & 31) == 0) {
        if (bg) atomicOr(&g_gt1, 1);
        if (bp) atomicOr(&g_pair, 1);
    }
}

// ---------------------------------------------------------------------------
// Per-output-block compacted nonzero k-block lists (validated).
// ---------------------------------------------------------------------------
__global__ void build_slots(const void* __restrict__ mask) {
    const int ob = blockIdx.x;
    const int kb = threadIdx.x;   // 0..255
    const bool elt4 = (g_gt1 != 0) || (g_pair == 0);
    size_t e = (size_t)(ob * 16) * KDIM + (size_t)kb * 16;
    bool nz = elt4 ? (((const unsigned*)mask)[e] != 0u)
                   : (((const unsigned char*)mask)[e] != 0);
    unsigned bal = __ballot_sync(0xFFFFFFFFu, nz);
    __shared__ int wcnt[8];
    int wid = kb >> 5, lane = kb & 31;
    if (lane == 0) wcnt[wid] = __popc(bal);
    __syncthreads();
    int off = 0;
    for (int i = 0; i < wid; ++i) off += wcnt[i];
    if (nz)
        g_oblist[ob * 256 + off + __popc(bal & ((1u << lane) - 1u))] =
            (unsigned char)kb;
    if (kb == 0) {
        int tot = 0;
        for (int i = 0; i < 8; ++i) tot += wcnt[i];
        g_obcnt[ob] = tot;
    }
}

// ---------------------------------------------------------------------------
// w -> bf16 hi/lo B-fragments (validated; permuted-k convention).
// ---------------------------------------------------------------------------
__global__ void prep_w(const float* __restrict__ w) {
    const int ob = blockIdx.x;
    const int ws = threadIdx.x >> 5;
    const int lane = threadIdx.x & 31;
    const int g = lane >> 2, t = lane & 3;
    const int cnt = g_obcnt[ob];
    uint4* dst = g_wc4 + (size_t)ob * 256 * 64;
    for (int s = ws; s < cnt; s += 8) {
        int kb = g_oblist[ob * 256 + s];
        const float* wr = w + (size_t)(ob * 16 + g) * KDIM + kb * 16 + t * 4;
        float4 v0 = *(const float4*)wr;              // n = g       (nf0)
        float4 v1 = *(const float4*)(wr + 8 * KDIM); // n = g + 8   (nf1)
        uint4 hi, lo;
        split2(v0.x, v0.y, hi.x, lo.x);
        split2(v0.z, v0.w, hi.y, lo.y);
        split2(v1.x, v1.y, hi.z, lo.z);
        split2(v1.z, v1.w, hi.w, lo.w);
        dst[(size_t)s * 64 + lane] = hi;
        dst[(size_t)s * 64 + 32 + lane] = lo;
    }
}

// ---------------------------------------------------------------------------
// x -> bf16 hi/lo A-fragments, k-block-major (validated R6).
// ---------------------------------------------------------------------------
__global__ void prep_x(const float* __restrict__ x) {
    const int kb = blockIdx.x;
    const int mt = blockIdx.y * 8 + (threadIdx.x >> 5);
    const int lane = threadIdx.x & 31;
    const int g = lane >> 2, t = lane & 3;
    const float* xr = x + (size_t)(mt * 16 + g) * KDIM + kb * 16 + t * 4;
    float4 v0 = *(const float4*)xr;                  // row g
    float4 v1 = *(const float4*)(xr + 8 * KDIM);     // row g+8
    uint4 hi, lo;
    split2(v0.x, v0.y, hi.x, lo.x);    // a0
    split2(v1.x, v1.y, hi.y, lo.y);    // a1
    split2(v0.z, v0.w, hi.z, lo.z);    // a2
    split2(v1.z, v1.w, hi.w, lo.w);    // a3
    uint4* dst = g_xf + ((size_t)kb * 512 + mt) * 64;
    dst[lane] = hi;
    dst[32 + lane] = lo;
}

// ---------------------------------------------------------------------------
// Main GEMM: grid (16 ob-groups, M/64), 512 threads = 16 warps.
//   warp w handles ob = bx*16 + w over the SAME 64-row slice -> the 16 warps
//   re-read the same x fragments (L1 hits) whenever k-lists overlap.
// Software-pipelined slot loop (validated R7).
// ---------------------------------------------------------------------------
__global__ void __launch_bounds__(512, 1)
bsgemm(const float* __restrict__ bias, float* __restrict__ out) {
    const int wid = threadIdx.x >> 5;
    const int ob = blockIdx.x * 16 + wid;
    const int m0 = blockIdx.y * 64;
    const int mt0 = blockIdx.y * 4;
    const int lane = threadIdx.x & 31;
    const int g = lane >> 2, t = lane & 3;

    float acc[32];
#pragma unroll
    for (int i = 0; i < 32; ++i) acc[i] = 0.0f;

    const int cnt = g_obcnt[ob];
    const unsigned char* lst = g_oblist + ob * 256;
    const uint4* wc = g_wc4 + (size_t)ob * 256 * 64;

    // ---- prologue: load slot 0 (safe even if cnt==0: in-bounds dummy) ----
    uint4 wh, wl, xh[4], xl[4];
    {
        const int kb0 = lst[0];
        wh = wc[lane];
        wl = wc[32 + lane];
        const uint4* xf = g_xf + ((size_t)kb0 * 512 + mt0) * 64;
#pragma unroll
        for (int tt = 0; tt < 4; ++tt) {
            xh[tt] = xf[tt * 64 + lane];
            xl[tt] = xf[tt * 64 + 32 + lane];
        }
    }

    for (int i = 0; i < cnt; ++i) {
        // ---- prefetch slot i+1 (clamped, stays in-bounds) ----
        const int ni = (i + 1 < cnt) ? (i + 1) : i;
        const int nkb = lst[ni];
        uint4 nwh = wc[(size_t)ni * 64 + lane];
        uint4 nwl = wc[(size_t)ni * 64 + 32 + lane];
        const uint4* nxf = g_xf + ((size_t)nkb * 512 + mt0) * 64;
        uint4 nxh[4], nxl[4];
#pragma unroll
        for (int tt = 0; tt < 4; ++tt) {
            nxh[tt] = nxf[tt * 64 + lane];
            nxl[tt] = nxf[tt * 64 + 32 + lane];
        }
        // ---- mma on current slot: 3-term hi/lo ----
#pragma unroll
        for (int mf = 0; mf < 4; ++mf) {
            const uint32_t* ah = reinterpret_cast<const uint32_t*>(&xh[mf]);
            const uint32_t* al = reinterpret_cast<const uint32_t*>(&xl[mf]);
            float* cA = acc + mf * 8;
            float* cB = acc + mf * 8 + 4;
            mma16816(cA, ah, wh.x, wh.y);
            mma16816(cA, ah, wl.x, wl.y);
            mma16816(cA, al, wh.x, wh.y);
            mma16816(cB, ah, wh.z, wh.w);
            mma16816(cB, ah, wl.z, wl.w);
            mma16816(cB, al, wh.z, wh.w);
        }
        // ---- rotate ----
        wh = nwh; wl = nwl;
#pragma unroll
        for (int tt = 0; tt < 4; ++tt) { xh[tt] = nxh[tt]; xl[tt] = nxl[tt]; }
    }

    // ---- epilogue: bias + direct STG.64 (validated) ----
    const float2 b0 = *(const float2*)(bias + ob * 16 + t * 2);
    const float2 b1 = *(const float2*)(bias + ob * 16 + 8 + t * 2);
#pragma unroll
    for (int mf = 0; mf < 4; ++mf) {
        const int r0 = m0 + mf * 16 + g;
        float* o0 = out + (size_t)r0 * NDIM + ob * 16 + t * 2;
        float* o1 = o0 + (size_t)8 * NDIM;
        *(float2*)o0       = make_float2(acc[mf * 8 + 0] + b0.x, acc[mf * 8 + 1] + b0.y);
        *(float2*)(o0 + 8) = make_float2(acc[mf * 8 + 4] + b1.x, acc[mf * 8 + 5] + b1.y);
        *(float2*)o1       = make_float2(acc[mf * 8 + 2] + b0.x, acc[mf * 8 + 3] + b0.y);
        *(float2*)(o1 + 8) = make_float2(acc[mf * 8 + 6] + b1.x, acc[mf * 8 + 7] + b1.y);
    }
}

// ---------------------------------------------------------------------------
extern "C" void kernel_launch(void* const* d_in, const int* in_sizes, int n_in,
                              void* d_out, int out_size) {
    const float* x    = (const float*)d_in[0];   // [8192, 4096] fp32
    const float* w    = (const float*)d_in[1];   // [4096, 4096] fp32
    const float* bias = (const float*)d_in[2];   // [4096] fp32
    const void*  mask = d_in[3];                 // [4096, 4096] bool/int/float
    float* out = (float*)d_out;                  // [8192, 4096] fp32

    const int M = in_sizes[0] / KDIM;            // 8192

    detect_mask_kernel<<<512, 256>>>((const unsigned char*)mask);
    build_slots<<<NOB, 256>>>(mask);
    prep_w<<<NOB, 256>>>(w);
    prep_x<<<dim3(256, M / 128), 256>>>(x);
    bsgemm<<<dim3(NOB / 16, M / 64), 512>>>(bias, out);
}

// round 14
// speedup vs baseline: 1.4561x; 1.4561x over previous
#include <cuda_runtime.h>
#include <cuda_bf16.h>
#include <cuda_fp16.h>
#include <cstdint>

// ============================================================================
// BlockSparseLinear: out[M=8192, N=4096] = x[M, K=4096] @ (W .* mask)^T + bias
// mask: 16x16 uniform blocks, ~10% nonzero.
//
// R14: R7 skeleton (241.8us, best) + fp16 2-term replacing bf16 3-term.
//   R13 post-mortem: L1-sharing regrouping REGRESSED (+25us) -> bsgemm is
//   bound by per-warp L1 wavefronts + tensor issue, NOT L2 BW. So: cut
//   per-warp bytes (10->6 LDG.128/slot) and MMAs (24->16/slot):
//     out = x16 * (wh + wl),  x single fp16, w fp16 hi/lo.
//   Error: x-rounding 2^-11 rms -> rel_err ~3e-4 (quadrature; method
//   validated on 3-term: predicted 1e-5, measured 4.7e-6). Threshold 1e-3.
//   - detect_mask, build_slots: validated R6
//   - CTA = 4 warps same ob x 64-row slices, pipelined slot loop: R7
// ============================================================================

#define KDIM 4096
#define NDIM 4096
#define NOB  256

__device__ int g_gt1, g_pair;          // sticky detection flags (idempotent)
__device__ int g_obcnt[NOB];
__device__ unsigned char g_oblist[NOB * 256];
// w fragments: per ob, per slot: [hi: 32 x uint4][lo: 32 x uint4] = 1 KB
__device__ __align__(16) uint4 g_wc4[(size_t)NOB * 256 * 64];
// x fragments (fp16 single): per (kb, mtile16): 32 x uint4 = 512 B
__device__ __align__(16) uint4 g_xf[(size_t)256 * 512 * 32];

// ---------------------------------------------------------------------------
__device__ __forceinline__ void split2h(float a, float b, uint32_t& h, uint32_t& l) {
    __half2 hh = __floats2half2_rn(a, b);
    float af = __low2float(hh), bf = __high2float(hh);
    __half2 ll = __floats2half2_rn(a - af, b - bf);
    h = *reinterpret_cast<uint32_t*>(&hh);
    l = *reinterpret_cast<uint32_t*>(&ll);
}

__device__ __forceinline__ void mma16816h(float* c, const uint32_t* a,
                                          uint32_t b0, uint32_t b1) {
    asm volatile("mma.sync.aligned.m16n8k16.row.col.f32.f16.f16.f32 "
                 "{%0,%1,%2,%3}, {%4,%5,%6,%7}, {%8,%9}, {%0,%1,%2,%3};"
                 : "+f"(c[0]), "+f"(c[1]), "+f"(c[2]), "+f"(c[3])
                 : "r"(a[0]), "r"(a[1]), "r"(a[2]), "r"(a[3]), "r"(b0), "r"(b1));
}

// ---------------------------------------------------------------------------
// Mask dtype detection — parallel (validated R6).
// ---------------------------------------------------------------------------
__global__ void detect_mask_kernel(const unsigned char* __restrict__ mask) {
    size_t base = ((size_t)blockIdx.x * blockDim.x + threadIdx.x) * 8;
    uint64_t v = *(const uint64_t*)(mask + base);
    unsigned char nxt = mask[base + 8];
    bool gt1 = false, pair = false;
#pragma unroll
    for (int j = 0; j < 8; ++j) {
        unsigned char a = (unsigned char)(v >> (8 * j));
        unsigned char b = (j < 7) ? (unsigned char)(v >> (8 * (j + 1))) : nxt;
        gt1 |= (a > 1);
        pair |= (a == 1 && b == 1);
    }
    unsigned bg = __ballot_sync(0xFFFFFFFFu, gt1);
    unsigned bp = __ballot_sync(0xFFFFFFFFu, pair);
    if ((threadIdx.x & 31) == 0) {
        if (bg) atomicOr(&g_gt1, 1);
        if (bp) atomicOr(&g_pair, 1);
    }
}

// ---------------------------------------------------------------------------
// Per-output-block compacted nonzero k-block lists (validated).
// ---------------------------------------------------------------------------
__global__ void build_slots(const void* __restrict__ mask) {
    const int ob = blockIdx.x;
    const int kb = threadIdx.x;   // 0..255
    const bool elt4 = (g_gt1 != 0) || (g_pair == 0);
    size_t e = (size_t)(ob * 16) * KDIM + (size_t)kb * 16;
    bool nz = elt4 ? (((const unsigned*)mask)[e] != 0u)
                   : (((const unsigned char*)mask)[e] != 0);
    unsigned bal = __ballot_sync(0xFFFFFFFFu, nz);
    __shared__ int wcnt[8];
    int wid = kb >> 5, lane = kb & 31;
    if (lane == 0) wcnt[wid] = __popc(bal);
    __syncthreads();
    int off = 0;
    for (int i = 0; i < wid; ++i) off += wcnt[i];
    if (nz)
        g_oblist[ob * 256 + off + __popc(bal & ((1u << lane) - 1u))] =
            (unsigned char)kb;
    if (kb == 0) {
        int tot = 0;
        for (int i = 0; i < 8; ++i) tot += wcnt[i];
        g_obcnt[ob] = tot;
    }
}

// ---------------------------------------------------------------------------
// w -> fp16 hi/lo B-fragments (permuted-k convention, layout as validated).
//   lane: g = lane>>2 (n within half), t = lane&3
//   hi uint4 = {nf0 b0, nf0 b1, nf1 b0, nf1 b1}
// ---------------------------------------------------------------------------
__global__ void prep_w(const float* __restrict__ w) {
    const int ob = blockIdx.x;
    const int ws = threadIdx.x >> 5;
    const int lane = threadIdx.x & 31;
    const int g = lane >> 2, t = lane & 3;
    const int cnt = g_obcnt[ob];
    uint4* dst = g_wc4 + (size_t)ob * 256 * 64;
    for (int s = ws; s < cnt; s += 8) {
        int kb = g_oblist[ob * 256 + s];
        const float* wr = w + (size_t)(ob * 16 + g) * KDIM + kb * 16 + t * 4;
        float4 v0 = *(const float4*)wr;              // n = g       (nf0)
        float4 v1 = *(const float4*)(wr + 8 * KDIM); // n = g + 8   (nf1)
        uint4 hi, lo;
        split2h(v0.x, v0.y, hi.x, lo.x);
        split2h(v0.z, v0.w, hi.y, lo.y);
        split2h(v1.x, v1.y, hi.z, lo.z);
        split2h(v1.z, v1.w, hi.w, lo.w);
        dst[(size_t)s * 64 + lane] = hi;
        dst[(size_t)s * 64 + 32 + lane] = lo;
    }
}

// ---------------------------------------------------------------------------
// x -> single fp16 A-fragments, k-block-major (permuted-k, layout as R6).
//   lane l (g=l>>2, t=l&3): a0 = rows mt*16+g,  k t*4..t*4+1
//                           a2 = rows mt*16+g,  k t*4+2..t*4+3
//                           a1/a3 = rows +8, same k
//   Tile (kb, mt): 32 x uint4 = 512 B.
// ---------------------------------------------------------------------------
__global__ void prep_x(const float* __restrict__ x) {
    const int kb = blockIdx.x;
    const int mt = blockIdx.y * 8 + (threadIdx.x >> 5);
    const int lane = threadIdx.x & 31;
    const int g = lane >> 2, t = lane & 3;
    const float* xr = x + (size_t)(mt * 16 + g) * KDIM + kb * 16 + t * 4;
    float4 v0 = *(const float4*)xr;                  // row g
    float4 v1 = *(const float4*)(xr + 8 * KDIM);     // row g+8
    uint4 hi;
    __half2 h;
    h = __floats2half2_rn(v0.x, v0.y); hi.x = *reinterpret_cast<uint32_t*>(&h); // a0
    h = __floats2half2_rn(v1.x, v1.y); hi.y = *reinterpret_cast<uint32_t*>(&h); // a1
    h = __floats2half2_rn(v0.z, v0.w); hi.z = *reinterpret_cast<uint32_t*>(&h); // a2
    h = __floats2half2_rn(v1.z, v1.w); hi.w = *reinterpret_cast<uint32_t*>(&h); // a3
    g_xf[((size_t)kb * 512 + mt) * 32 + lane] = hi;
}

// ---------------------------------------------------------------------------
// Main GEMM: grid (256 obs, M/256), 128 threads (4 warps x 64 M rows) — R7
// shape. Pipelined slot loop: 6 LDG.128 prefetch + 16 MMAs per slot.
// ---------------------------------------------------------------------------
__global__ void __launch_bounds__(128, 4)
bsgemm(const float* __restrict__ bias, float* __restrict__ out) {
    const int ob = blockIdx.x;
    const int wid = threadIdx.x >> 5;
    const int m0 = blockIdx.y * 256 + wid * 64;
    const int mt0 = blockIdx.y * 16 + wid * 4;
    const int lane = threadIdx.x & 31;
    const int g = lane >> 2, t = lane & 3;

    float acc[32];
#pragma unroll
    for (int i = 0; i < 32; ++i) acc[i] = 0.0f;

    const int cnt = g_obcnt[ob];
    const unsigned char* lst = g_oblist + ob * 256;
    const uint4* wc = g_wc4 + (size_t)ob * 256 * 64;

    // ---- prologue: load slot 0 (in-bounds dummy if cnt==0) ----
    uint4 wh, wl, xh[4];
    {
        const int kb0 = lst[0];
        wh = wc[lane];
        wl = wc[32 + lane];
        const uint4* xf = g_xf + ((size_t)kb0 * 512 + mt0) * 32;
#pragma unroll
        for (int tt = 0; tt < 4; ++tt) xh[tt] = xf[tt * 32 + lane];
    }

    for (int i = 0; i < cnt; ++i) {
        // ---- prefetch slot i+1 (clamped, in-bounds) ----
        const int ni = (i + 1 < cnt) ? (i + 1) : i;
        const int nkb = lst[ni];
        uint4 nwh = wc[(size_t)ni * 64 + lane];
        uint4 nwl = wc[(size_t)ni * 64 + 32 + lane];
        const uint4* nxf = g_xf + ((size_t)nkb * 512 + mt0) * 32;
        uint4 nxh[4];
#pragma unroll
        for (int tt = 0; tt < 4; ++tt) nxh[tt] = nxf[tt * 32 + lane];

        // ---- mma: 2-term x16*(wh + wl) ----
#pragma unroll
        for (int mf = 0; mf < 4; ++mf) {
            const uint32_t* ah = reinterpret_cast<const uint32_t*>(&xh[mf]);
            float* cA = acc + mf * 8;
            float* cB = acc + mf * 8 + 4;
            mma16816h(cA, ah, wh.x, wh.y);
            mma16816h(cA, ah, wl.x, wl.y);
            mma16816h(cB, ah, wh.z, wh.w);
            mma16816h(cB, ah, wl.z, wl.w);
        }
        // ---- rotate ----
        wh = nwh; wl = nwl;
#pragma unroll
        for (int tt = 0; tt < 4; ++tt) xh[tt] = nxh[tt];
    }

    // ---- epilogue: bias + direct STG.64 (validated) ----
    const float2 b0 = *(const float2*)(bias + ob * 16 + t * 2);
    const float2 b1 = *(const float2*)(bias + ob * 16 + 8 + t * 2);
#pragma unroll
    for (int mf = 0; mf < 4; ++mf) {
        const int r0 = m0 + mf * 16 + g;
        float* o0 = out + (size_t)r0 * NDIM + ob * 16 + t * 2;
        float* o1 = o0 + (size_t)8 * NDIM;
        *(float2*)o0       = make_float2(acc[mf * 8 + 0] + b0.x, acc[mf * 8 + 1] + b0.y);
        *(float2*)(o0 + 8) = make_float2(acc[mf * 8 + 4] + b1.x, acc[mf * 8 + 5] + b1.y);
        *(float2*)o1       = make_float2(acc[mf * 8 + 2] + b0.x, acc[mf * 8 + 3] + b0.y);
        *(float2*)(o1 + 8) = make_float2(acc[mf * 8 + 6] + b1.x, acc[mf * 8 + 7] + b1.y);
    }
}

// ---------------------------------------------------------------------------
extern "C" void kernel_launch(void* const* d_in, const int* in_sizes, int n_in,
                              void* d_out, int out_size) {
    const float* x    = (const float*)d_in[0];   // [8192, 4096] fp32
    const float* w    = (const float*)d_in[1];   // [4096, 4096] fp32
    const float* bias = (const float*)d_in[2];   // [4096] fp32
    const void*  mask = d_in[3];                 // [4096, 4096] bool/int/float
    float* out = (float*)d_out;                  // [8192, 4096] fp32

    const int M = in_sizes[0] / KDIM;            // 8192

    detect_mask_kernel<<<512, 256>>>((const unsigned char*)mask);
    build_slots<<<NOB, 256>>>(mask);
    prep_w<<<NOB, 256>>>(w);
    prep_x<<<dim3(256, M / 128), 256>>>(x);
    bsgemm<<<dim3(NOB, M / 256), 128>>>(bias, out);
}